// round 2
// baseline (speedup 1.0000x reference)
#include <cuda_runtime.h>
#include <math.h>

#define N_NODES 100000
#define N_EDGES 3200000
#define IN_DIM 512
#define HIDDEN 16
#define N_CLASSES 7
#define NBLK 391          // ceil(100000/256)

// ---------------- scratch (device globals; no allocation) ----------------
__device__ int   g_deg[N_NODES];
__device__ int   g_rowptr[N_NODES + 1];
__device__ int   g_fill[N_NODES];
__device__ int   g_adj[N_EDGES];
__device__ float g_dinv[N_NODES];
__device__ int   g_bsum[NBLK];
__device__ int   g_boff[NBLK];
__device__ float g_h1[N_NODES * HIDDEN];    // dinv[i] * (x@W1)[i]
__device__ float g_y2[N_NODES * N_CLASSES]; // dinv[i] * (relu(...)@W2)[i]

// ---------------- packed f32x2 FMA (sm_100+) ----------------
__device__ __forceinline__ void fma2(float2& acc, float2 a, float2 b) {
    asm("fma.rn.f32x2 %0, %1, %2, %0;"
        : "+l"(*reinterpret_cast<unsigned long long*>(&acc))
        : "l"(*reinterpret_cast<unsigned long long*>(&a)),
          "l"(*reinterpret_cast<unsigned long long*>(&b)));
}

// ---------------- CSR build ----------------
__global__ void k_zero_deg() {
    int i = blockIdx.x * blockDim.x + threadIdx.x;
    if (i < N_NODES) g_deg[i] = 0;
}

__global__ void k_count(const int* __restrict__ ei) {
    int e = blockIdx.x * blockDim.x + threadIdx.x;
    if (e < N_EDGES) atomicAdd(&g_deg[ei[N_EDGES + e]], 1);
}

// pass 1: per-block sums of deg
__global__ void k_s1() {
    int t = threadIdx.x;
    int i = blockIdx.x * 256 + t;
    int lane = t & 31, w = t >> 5;
    int v = (i < N_NODES) ? g_deg[i] : 0;
    #pragma unroll
    for (int o = 16; o > 0; o >>= 1) v += __shfl_down_sync(0xffffffffu, v, o);
    __shared__ int ws[8];
    if (lane == 0) ws[w] = v;
    __syncthreads();
    if (t == 0) {
        int s = 0;
        #pragma unroll
        for (int k = 0; k < 8; k++) s += ws[k];
        g_bsum[blockIdx.x] = s;
    }
}

// pass 2: exclusive scan of the 391 block sums (one block, 512 threads)
__global__ void k_s2() {
    int t = threadIdx.x, lane = t & 31, w = t >> 5;
    int v = (t < NBLK) ? g_bsum[t] : 0;
    int x = v;
    #pragma unroll
    for (int o = 1; o < 32; o <<= 1) {
        int u = __shfl_up_sync(0xffffffffu, x, o);
        if (lane >= o) x += u;
    }
    __shared__ int ws[16], wsp[16];
    if (lane == 31) ws[w] = x;
    __syncthreads();
    if (t < 16) {
        int s = ws[t];
        #pragma unroll
        for (int o = 1; o < 16; o <<= 1) {
            int u = __shfl_up_sync(0x0000ffffu, s, o);
            if (t >= o) s += u;
        }
        wsp[t] = s;
    }
    __syncthreads();
    int incl = x + (w > 0 ? wsp[w - 1] : 0);
    if (t < NBLK) g_boff[t] = incl - v;
    if (t == NBLK - 1) g_rowptr[N_NODES] = incl;
}

// pass 3: block-local exclusive scan + block offset -> rowptr; fused prep
__global__ void k_s3() {
    int t = threadIdx.x;
    int i = blockIdx.x * 256 + t;
    int lane = t & 31, w = t >> 5;
    int v = (i < N_NODES) ? g_deg[i] : 0;
    int x = v;
    #pragma unroll
    for (int o = 1; o < 32; o <<= 1) {
        int u = __shfl_up_sync(0xffffffffu, x, o);
        if (lane >= o) x += u;
    }
    __shared__ int ws[8], wsp[8];
    if (lane == 31) ws[w] = x;
    __syncthreads();
    if (t < 8) {
        int s = ws[t];
        #pragma unroll
        for (int o = 1; o < 8; o <<= 1) {
            int u = __shfl_up_sync(0x000000ffu, s, o);
            if (t >= o) s += u;
        }
        wsp[t] = s;
    }
    __syncthreads();
    int excl = x - v + (w > 0 ? wsp[w - 1] : 0) + g_boff[blockIdx.x];
    if (i < N_NODES) {
        g_rowptr[i] = excl;
        g_fill[i] = excl;
        g_dinv[i] = rsqrtf((float)(v + 1));  // +1 self loop
    }
}

__global__ void k_fill(const int* __restrict__ ei) {
    int e = blockIdx.x * blockDim.x + threadIdx.x;
    if (e < N_EDGES) {
        int s = ei[e];
        int d = ei[N_EDGES + e];
        int p = atomicAdd(&g_fill[d], 1);
        g_adj[p] = s;
    }
}

// ---------------- GEMM1: g_h1 = dinv * (x @ W1) ----------------
// BM=512 rows/block, BK=16, 256 threads. TM=8 (rows strided by 64) x TN=4.
// f32x2 FMAs with k-paired accumulators: acc.x = even-k partial, acc.y = odd-k.
#define GM 512

__global__ __launch_bounds__(256) void k_gemm1(const float* __restrict__ x,
                                               const float* __restrict__ W1) {
    __shared__ __align__(16) float4 xs4[4][GM];   // xs4[k4][row] = x[row][k0+4*k4 ..]
    __shared__ __align__(16) float  wsT[HIDDEN][16]; // wsT[c][kk] = W1[k0+kk][c]
    int tid = threadIdx.x;
    int rg = tid & 63;        // row group 0..63
    int cg = tid >> 6;        // col group 0..3 (cols cg*4..cg*4+3)
    int row0 = blockIdx.x * GM;

    float2 acc[8][4];
    #pragma unroll
    for (int i = 0; i < 8; i++)
        #pragma unroll
        for (int c = 0; c < 4; c++) acc[i][c] = make_float2(0.f, 0.f);

    for (int k0 = 0; k0 < IN_DIM; k0 += 16) {
        // stage x tile: 512 rows x 16 k as 2048 float4s
        #pragma unroll
        for (int it = 0; it < 8; it++) {
            int f = tid + it * 256;
            int r = f >> 2;
            int k4 = f & 3;
            int gr = row0 + r;
            float4 v = make_float4(0.f, 0.f, 0.f, 0.f);
            if (gr < N_NODES)
                v = *(const float4*)&x[(size_t)gr * IN_DIM + k0 + k4 * 4];
            xs4[k4][r] = v;
        }
        // stage W tile transposed (k contiguous per col)
        {
            int c = tid >> 4, kk = tid & 15;
            wsT[c][kk] = W1[(k0 + kk) * HIDDEN + c];
        }
        __syncthreads();

        #pragma unroll
        for (int k4 = 0; k4 < 4; k4++) {
            // whole warp reads the same 4 cols -> smem broadcast (free)
            float4 wv0 = *(const float4*)&wsT[cg * 4 + 0][k4 * 4];
            float4 wv1 = *(const float4*)&wsT[cg * 4 + 1][k4 * 4];
            float4 wv2 = *(const float4*)&wsT[cg * 4 + 2][k4 * 4];
            float4 wv3 = *(const float4*)&wsT[cg * 4 + 3][k4 * 4];
            #pragma unroll
            for (int i = 0; i < 8; i++) {
                float4 xv = xs4[k4][rg + 64 * i];
                float2 xlo = make_float2(xv.x, xv.y);
                float2 xhi = make_float2(xv.z, xv.w);
                fma2(acc[i][0], xlo, make_float2(wv0.x, wv0.y));
                fma2(acc[i][0], xhi, make_float2(wv0.z, wv0.w));
                fma2(acc[i][1], xlo, make_float2(wv1.x, wv1.y));
                fma2(acc[i][1], xhi, make_float2(wv1.z, wv1.w));
                fma2(acc[i][2], xlo, make_float2(wv2.x, wv2.y));
                fma2(acc[i][2], xhi, make_float2(wv2.z, wv2.w));
                fma2(acc[i][3], xlo, make_float2(wv3.x, wv3.y));
                fma2(acc[i][3], xhi, make_float2(wv3.z, wv3.w));
            }
        }
        __syncthreads();
    }

    #pragma unroll
    for (int i = 0; i < 8; i++) {
        int r = row0 + rg + 64 * i;
        if (r < N_NODES) {
            float dv = g_dinv[r];
            float4 o = make_float4(dv * (acc[i][0].x + acc[i][0].y),
                                   dv * (acc[i][1].x + acc[i][1].y),
                                   dv * (acc[i][2].x + acc[i][2].y),
                                   dv * (acc[i][3].x + acc[i][3].y));
            *(float4*)&g_h1[r * HIDDEN + cg * 4] = o;
        }
    }
}

// ---------------- Layer-1 aggregation + relu + W2 GEMM fused ----------------
// half-warp (16 lanes) per node; lane j = feature j. Neighbor indices are
// read with uniform (broadcast) loads -- no shuffles in the hot loop.
__global__ __launch_bounds__(256) void k_agg1(const float* __restrict__ b1,
                                              const float* __restrict__ W2) {
    __shared__ float sW2[HIDDEN * N_CLASSES];
    __shared__ float sb1[HIDDEN];
    int tid = threadIdx.x;
    if (tid < HIDDEN * N_CLASSES) sW2[tid] = W2[tid];
    if (tid < HIDDEN) sb1[tid] = b1[tid];
    __syncthreads();

    int lane = tid & 31;
    int wid = tid >> 5;
    int half = lane >> 4;
    int j = lane & 15;
    int node = (blockIdx.x * 8 + wid) * 2 + half;
    if (node >= N_NODES) return;
    unsigned mask = 0xFFFFu << (half * 16);

    float acc = g_h1[node * HIDDEN + j];   // self-loop term
    int pos = g_rowptr[node];
    int end = g_rowptr[node + 1];
    int i = pos;
    for (; i + 4 <= end; i += 4) {
        int s0 = __ldg(&g_adj[i]);
        int s1 = __ldg(&g_adj[i + 1]);
        int s2 = __ldg(&g_adj[i + 2]);
        int s3 = __ldg(&g_adj[i + 3]);
        float v0 = g_h1[s0 * HIDDEN + j];
        float v1 = g_h1[s1 * HIDDEN + j];
        float v2 = g_h1[s2 * HIDDEN + j];
        float v3 = g_h1[s3 * HIDDEN + j];
        acc += (v0 + v1) + (v2 + v3);
    }
    for (; i < end; i++)
        acc += g_h1[__ldg(&g_adj[i]) * HIDDEN + j];

    float dv = g_dinv[node];
    float y = fmaxf(dv * acc + sb1[j], 0.f);  // relu(agg + b1)

    // fused layer-2 GEMM: g_y2[node][c] = dv * sum_j y_j * W2[j][c]
    #pragma unroll
    for (int c = 0; c < N_CLASSES; c++) {
        float t = y * sW2[j * N_CLASSES + c];
        t += __shfl_xor_sync(mask, t, 1);
        t += __shfl_xor_sync(mask, t, 2);
        t += __shfl_xor_sync(mask, t, 4);
        t += __shfl_xor_sync(mask, t, 8);
        if (j == c) g_y2[node * N_CLASSES + c] = dv * t;
    }
}

// ---------------- Layer-2 aggregation + bias + log_softmax ----------------
// 8 lanes per node (7 active features); 4 nodes per warp
__global__ __launch_bounds__(256) void k_agg2(const float* __restrict__ b2,
                                              float* __restrict__ out) {
    int tid = threadIdx.x;
    int lane = tid & 31;
    int wid = tid >> 5;
    int sub = lane >> 3;            // 0..3
    int j = lane & 7;               // 0..7 (lane 7 inactive for data)
    int node = (blockIdx.x * 8 + wid) * 4 + sub;
    if (node >= N_NODES) return;
    unsigned mask = 0xFFu << (sub * 8);
    int jr = (j < N_CLASSES) ? j : 0;

    float acc = (j < N_CLASSES) ? g_y2[node * N_CLASSES + j] : 0.f;
    int pos = g_rowptr[node];
    int end = g_rowptr[node + 1];
    int i = pos;
    for (; i + 4 <= end; i += 4) {
        int s0 = __ldg(&g_adj[i]);
        int s1 = __ldg(&g_adj[i + 1]);
        int s2 = __ldg(&g_adj[i + 2]);
        int s3 = __ldg(&g_adj[i + 3]);
        float v0 = g_y2[s0 * N_CLASSES + jr];
        float v1 = g_y2[s1 * N_CLASSES + jr];
        float v2 = g_y2[s2 * N_CLASSES + jr];
        float v3 = g_y2[s3 * N_CLASSES + jr];
        acc += (v0 + v1) + (v2 + v3);
    }
    for (; i < end; i++)
        acc += g_y2[__ldg(&g_adj[i]) * N_CLASSES + jr];

    float dv = g_dinv[node];
    float o = dv * acc + ((j < N_CLASSES) ? __ldg(&b2[jr]) : 0.f);

    // log_softmax across the 7 active lanes of this 8-lane group
    float m = (j < N_CLASSES) ? o : -1e30f;
    m = fmaxf(m, __shfl_xor_sync(mask, m, 1));
    m = fmaxf(m, __shfl_xor_sync(mask, m, 2));
    m = fmaxf(m, __shfl_xor_sync(mask, m, 4));
    float e = (j < N_CLASSES) ? expf(o - m) : 0.f;
    float s = e;
    s += __shfl_xor_sync(mask, s, 1);
    s += __shfl_xor_sync(mask, s, 2);
    s += __shfl_xor_sync(mask, s, 4);
    float ls = logf(s);
    if (j < N_CLASSES) out[node * N_CLASSES + j] = o - m - ls;
}

// ---------------- launch ----------------
extern "C" void kernel_launch(void* const* d_in, const int* in_sizes, int n_in,
                              void* d_out, int out_size) {
    const float* x  = (const float*)d_in[0];
    const int*   ei = (const int*)d_in[1];
    const float* W1 = (const float*)d_in[2];
    const float* b1 = (const float*)d_in[3];
    const float* W2 = (const float*)d_in[4];
    const float* b2 = (const float*)d_in[5];
    float* out = (float*)d_out;

    const int TB = 256;
    int gridN = (N_NODES + TB - 1) / TB;     // 391
    int gridE = (N_EDGES + TB - 1) / TB;

    k_zero_deg<<<gridN, TB>>>();
    k_count<<<gridE, TB>>>(ei);
    k_s1<<<NBLK, 256>>>();
    k_s2<<<1, 512>>>();
    k_s3<<<NBLK, 256>>>();
    k_fill<<<gridE, TB>>>(ei);

    int gridG = (N_NODES + GM - 1) / GM;     // 196
    k_gemm1<<<gridG, 256>>>(x, W1);

    int grid1 = (N_NODES + 16 - 1) / 16;     // 16 nodes/block
    k_agg1<<<grid1, 256>>>(b1, W2);

    int grid2 = (N_NODES + 32 - 1) / 32;     // 32 nodes/block
    k_agg2<<<grid2, 256>>>(b2, out);
}

// round 3
// speedup vs baseline: 1.2873x; 1.2873x over previous
#include <cuda_runtime.h>
#include <math.h>

#define N_NODES 100000
#define N_EDGES 3200000
#define IN_DIM 512
#define HIDDEN 16
#define N_CLASSES 7
#define NBLK 391          // ceil(100000/256)

// ---------------- scratch (device globals; no allocation) ----------------
__device__ int   g_deg[N_NODES];
__device__ int   g_rowptr[N_NODES + 1];
__device__ int   g_fill[N_NODES];
__device__ int   g_adj[N_EDGES];
__device__ float g_dinv[N_NODES];
__device__ int   g_bsum[NBLK];
__device__ int   g_boff[NBLK];
__device__ float g_h1[N_NODES * HIDDEN];    // dinv[i] * (x@W1)[i]
__device__ float g_y2[N_NODES * N_CLASSES]; // dinv[i] * (relu(...)@W2)[i]

// ---------------- CSR build ----------------
__global__ void k_zero_deg() {
    int i = blockIdx.x * blockDim.x + threadIdx.x;
    if (i < N_NODES) g_deg[i] = 0;
}

__global__ void k_count(const int* __restrict__ ei) {
    int e = blockIdx.x * blockDim.x + threadIdx.x;
    if (e < N_EDGES) atomicAdd(&g_deg[ei[N_EDGES + e]], 1);
}

// pass 1: per-block sums of deg
__global__ void k_s1() {
    int t = threadIdx.x;
    int i = blockIdx.x * 256 + t;
    int lane = t & 31, w = t >> 5;
    int v = (i < N_NODES) ? g_deg[i] : 0;
    #pragma unroll
    for (int o = 16; o > 0; o >>= 1) v += __shfl_down_sync(0xffffffffu, v, o);
    __shared__ int ws[8];
    if (lane == 0) ws[w] = v;
    __syncthreads();
    if (t == 0) {
        int s = 0;
        #pragma unroll
        for (int k = 0; k < 8; k++) s += ws[k];
        g_bsum[blockIdx.x] = s;
    }
}

// pass 2: exclusive scan of the 391 block sums (one block, 512 threads)
__global__ void k_s2() {
    int t = threadIdx.x, lane = t & 31, w = t >> 5;
    int v = (t < NBLK) ? g_bsum[t] : 0;
    int x = v;
    #pragma unroll
    for (int o = 1; o < 32; o <<= 1) {
        int u = __shfl_up_sync(0xffffffffu, x, o);
        if (lane >= o) x += u;
    }
    __shared__ int ws[16], wsp[16];
    if (lane == 31) ws[w] = x;
    __syncthreads();
    if (t < 16) {
        int s = ws[t];
        #pragma unroll
        for (int o = 1; o < 16; o <<= 1) {
            int u = __shfl_up_sync(0x0000ffffu, s, o);
            if (t >= o) s += u;
        }
        wsp[t] = s;
    }
    __syncthreads();
    int incl = x + (w > 0 ? wsp[w - 1] : 0);
    if (t < NBLK) g_boff[t] = incl - v;
    if (t == NBLK - 1) g_rowptr[N_NODES] = incl;
}

// pass 3: block-local exclusive scan + block offset -> rowptr; fused prep
__global__ void k_s3() {
    int t = threadIdx.x;
    int i = blockIdx.x * 256 + t;
    int lane = t & 31, w = t >> 5;
    int v = (i < N_NODES) ? g_deg[i] : 0;
    int x = v;
    #pragma unroll
    for (int o = 1; o < 32; o <<= 1) {
        int u = __shfl_up_sync(0xffffffffu, x, o);
        if (lane >= o) x += u;
    }
    __shared__ int ws[8], wsp[8];
    if (lane == 31) ws[w] = x;
    __syncthreads();
    if (t < 8) {
        int s = ws[t];
        #pragma unroll
        for (int o = 1; o < 8; o <<= 1) {
            int u = __shfl_up_sync(0x000000ffu, s, o);
            if (t >= o) s += u;
        }
        wsp[t] = s;
    }
    __syncthreads();
    int excl = x - v + (w > 0 ? wsp[w - 1] : 0) + g_boff[blockIdx.x];
    if (i < N_NODES) {
        g_rowptr[i] = excl;
        g_fill[i] = excl;
        g_dinv[i] = rsqrtf((float)(v + 1));  // +1 self loop
    }
}

__global__ void k_fill(const int* __restrict__ ei) {
    int e = blockIdx.x * blockDim.x + threadIdx.x;
    if (e < N_EDGES) {
        int s = ei[e];
        int d = ei[N_EDGES + e];
        int p = atomicAdd(&g_fill[d], 1);
        g_adj[p] = s;
    }
}

// ---------------- GEMM1: g_h1 = dinv * (x @ W1) ----------------
// BM=256 rows/block, BN=16 (all cols), BK=16. 256 threads, each TM=4 x TN=4.
// (R1 version -- measured good; R2 f32x2 rewrite regressed.)
#define BM 256
#define BK 16
#define XS_PAD 4

__global__ __launch_bounds__(256) void k_gemm1(const float* __restrict__ x,
                                               const float* __restrict__ W1) {
    __shared__ float xs[BK][BM + XS_PAD];   // transposed: xs[k][row]
    __shared__ float ws[BK][HIDDEN];
    int tid = threadIdx.x;
    int rg = tid & 63;       // row group: rows rg*4 .. rg*4+3
    int cg = tid >> 6;       // col group: cols cg*4 .. cg*4+3
    int row0 = blockIdx.x * BM;

    float acc[4][4] = {};

    for (int k0 = 0; k0 < IN_DIM; k0 += BK) {
        // stage x tile (256 rows x 16 k), transposed into smem
        #pragma unroll
        for (int it = 0; it < 4; it++) {
            int f = tid + it * 256;      // 0..1023 float4 slots
            int r = f >> 2;
            int kk = (f & 3) << 2;
            int grow = row0 + r;
            float4 v = make_float4(0.f, 0.f, 0.f, 0.f);
            if (grow < N_NODES)
                v = *(const float4*)&x[(size_t)grow * IN_DIM + k0 + kk];
            xs[kk + 0][r] = v.x;
            xs[kk + 1][r] = v.y;
            xs[kk + 2][r] = v.z;
            xs[kk + 3][r] = v.w;
        }
        // stage W1 tile (16 k x 16 j)
        {
            int k = tid >> 4, j = tid & 15;
            ws[k][j] = W1[(k0 + k) * HIDDEN + j];
        }
        __syncthreads();
        #pragma unroll
        for (int k = 0; k < BK; k++) {
            float4 xv = *(const float4*)&xs[k][rg * 4];
            float4 wv = *(const float4*)&ws[k][cg * 4];
            acc[0][0] += xv.x * wv.x; acc[0][1] += xv.x * wv.y; acc[0][2] += xv.x * wv.z; acc[0][3] += xv.x * wv.w;
            acc[1][0] += xv.y * wv.x; acc[1][1] += xv.y * wv.y; acc[1][2] += xv.y * wv.z; acc[1][3] += xv.y * wv.w;
            acc[2][0] += xv.z * wv.x; acc[2][1] += xv.z * wv.y; acc[2][2] += xv.z * wv.z; acc[2][3] += xv.z * wv.w;
            acc[3][0] += xv.w * wv.x; acc[3][1] += xv.w * wv.y; acc[3][2] += xv.w * wv.z; acc[3][3] += xv.w * wv.w;
        }
        __syncthreads();
    }

    #pragma unroll
    for (int i = 0; i < 4; i++) {
        int r = row0 + rg * 4 + i;
        if (r < N_NODES) {
            float dv = g_dinv[r];
            float4 o = make_float4(acc[i][0] * dv, acc[i][1] * dv,
                                   acc[i][2] * dv, acc[i][3] * dv);
            *(float4*)&g_h1[r * HIDDEN + cg * 4] = o;
        }
    }
}

// ---------------- Layer-1 aggregation + relu + W2 GEMM fused ----------------
// half-warp (16 lanes) per node; lane j = feature j. (R1 shuffle scheme,
// deeper unroll for MLP.)
__global__ __launch_bounds__(256) void k_agg1(const float* __restrict__ b1,
                                              const float* __restrict__ W2) {
    __shared__ float sW2[HIDDEN * N_CLASSES];
    __shared__ float sb1[HIDDEN];
    int tid = threadIdx.x;
    if (tid < HIDDEN * N_CLASSES) sW2[tid] = W2[tid];
    if (tid < HIDDEN) sb1[tid] = b1[tid];
    __syncthreads();

    int lane = tid & 31;
    int wid = tid >> 5;
    int half = lane >> 4;
    int j = lane & 15;
    int node = (blockIdx.x * 8 + wid) * 2 + half;
    if (node >= N_NODES) return;
    unsigned mask = 0xFFFFu << (half * 16);
    int base = half * 16;

    float acc = g_h1[node * HIDDEN + j];   // self-loop term (g form)
    int pos = g_rowptr[node];
    int end = g_rowptr[node + 1];
    while (pos < end) {
        int cnt = end - pos;
        if (cnt > 16) cnt = 16;
        int src = (j < cnt) ? g_adj[pos + j] : 0;
        int i = 0;
        for (; i + 8 <= cnt; i += 8) {
            int s0 = __shfl_sync(mask, src, base + i);
            int s1 = __shfl_sync(mask, src, base + i + 1);
            int s2 = __shfl_sync(mask, src, base + i + 2);
            int s3 = __shfl_sync(mask, src, base + i + 3);
            int s4 = __shfl_sync(mask, src, base + i + 4);
            int s5 = __shfl_sync(mask, src, base + i + 5);
            int s6 = __shfl_sync(mask, src, base + i + 6);
            int s7 = __shfl_sync(mask, src, base + i + 7);
            float v0 = g_h1[s0 * HIDDEN + j];
            float v1 = g_h1[s1 * HIDDEN + j];
            float v2 = g_h1[s2 * HIDDEN + j];
            float v3 = g_h1[s3 * HIDDEN + j];
            float v4 = g_h1[s4 * HIDDEN + j];
            float v5 = g_h1[s5 * HIDDEN + j];
            float v6 = g_h1[s6 * HIDDEN + j];
            float v7 = g_h1[s7 * HIDDEN + j];
            acc += ((v0 + v1) + (v2 + v3)) + ((v4 + v5) + (v6 + v7));
        }
        for (; i < cnt; i++) {
            int s = __shfl_sync(mask, src, base + i);
            acc += g_h1[s * HIDDEN + j];
        }
        pos += cnt;
    }

    float dv = g_dinv[node];
    float y = fmaxf(dv * acc + sb1[j], 0.f);  // relu(agg + b1)

    // fused layer-2 GEMM: g_y2[node][c] = dv * sum_j y_j * W2[j][c]
    #pragma unroll
    for (int c = 0; c < N_CLASSES; c++) {
        float t = y * sW2[j * N_CLASSES + c];
        t += __shfl_xor_sync(mask, t, 1);
        t += __shfl_xor_sync(mask, t, 2);
        t += __shfl_xor_sync(mask, t, 4);
        t += __shfl_xor_sync(mask, t, 8);
        if (j == c) g_y2[node * N_CLASSES + c] = dv * t;
    }
}

// ---------------- Layer-2 aggregation + bias + log_softmax ----------------
// 8 lanes per node (7 active features); 4 nodes per warp  (R1 version)
__global__ __launch_bounds__(256) void k_agg2(const float* __restrict__ b2,
                                              float* __restrict__ out) {
    int tid = threadIdx.x;
    int lane = tid & 31;
    int wid = tid >> 5;
    int sub = lane >> 3;            // 0..3
    int j = lane & 7;               // 0..7 (lane 7 inactive for data)
    int node = (blockIdx.x * 8 + wid) * 4 + sub;
    if (node >= N_NODES) return;
    unsigned mask = 0xFFu << (sub * 8);
    int base = sub * 8;
    int jr = (j < N_CLASSES) ? j : 0;

    float acc = (j < N_CLASSES) ? g_y2[node * N_CLASSES + j] : 0.f;
    int pos = g_rowptr[node];
    int end = g_rowptr[node + 1];
    while (pos < end) {
        int cnt = end - pos;
        if (cnt > 8) cnt = 8;
        int src = (j < cnt) ? g_adj[pos + j] : 0;
        int i = 0;
        for (; i + 4 <= cnt; i += 4) {
            int s0 = __shfl_sync(mask, src, base + i);
            int s1 = __shfl_sync(mask, src, base + i + 1);
            int s2 = __shfl_sync(mask, src, base + i + 2);
            int s3 = __shfl_sync(mask, src, base + i + 3);
            float v0 = g_y2[s0 * N_CLASSES + jr];
            float v1 = g_y2[s1 * N_CLASSES + jr];
            float v2 = g_y2[s2 * N_CLASSES + jr];
            float v3 = g_y2[s3 * N_CLASSES + jr];
            acc += (v0 + v1) + (v2 + v3);
        }
        for (; i < cnt; i++) {
            int s = __shfl_sync(mask, src, base + i);
            acc += g_y2[s * N_CLASSES + jr];
        }
        pos += cnt;
    }

    float dv = g_dinv[node];
    float o = dv * acc + ((j < N_CLASSES) ? __ldg(&b2[jr]) : 0.f);

    // log_softmax across the 7 active lanes of this 8-lane group
    float m = (j < N_CLASSES) ? o : -1e30f;
    m = fmaxf(m, __shfl_xor_sync(mask, m, 1));
    m = fmaxf(m, __shfl_xor_sync(mask, m, 2));
    m = fmaxf(m, __shfl_xor_sync(mask, m, 4));
    float e = (j < N_CLASSES) ? expf(o - m) : 0.f;
    float s = e;
    s += __shfl_xor_sync(mask, s, 1);
    s += __shfl_xor_sync(mask, s, 2);
    s += __shfl_xor_sync(mask, s, 4);
    float ls = logf(s);
    if (j < N_CLASSES) out[node * N_CLASSES + j] = o - m - ls;
}

// ---------------- launch ----------------
extern "C" void kernel_launch(void* const* d_in, const int* in_sizes, int n_in,
                              void* d_out, int out_size) {
    const float* x  = (const float*)d_in[0];
    const int*   ei = (const int*)d_in[1];
    const float* W1 = (const float*)d_in[2];
    const float* b1 = (const float*)d_in[3];
    const float* W2 = (const float*)d_in[4];
    const float* b2 = (const float*)d_in[5];
    float* out = (float*)d_out;

    const int TB = 256;
    int gridN = (N_NODES + TB - 1) / TB;     // 391
    int gridE = (N_EDGES + TB - 1) / TB;

    k_zero_deg<<<gridN, TB>>>();
    k_count<<<gridE, TB>>>(ei);
    k_s1<<<NBLK, 256>>>();
    k_s2<<<1, 512>>>();
    k_s3<<<NBLK, 256>>>();
    k_fill<<<gridE, TB>>>(ei);

    int gridG = (N_NODES + BM - 1) / BM;     // 391
    k_gemm1<<<gridG, 256>>>(x, W1);

    int grid1 = (N_NODES + 16 - 1) / 16;     // 16 nodes/block
    k_agg1<<<grid1, 256>>>(b1, W2);

    int grid2 = (N_NODES + 32 - 1) / 32;     // 32 nodes/block
    k_agg2<<<grid2, 256>>>(b2, out);
}